// round 17
// baseline (speedup 1.0000x reference)
#include <cuda_runtime.h>
#include <math.h>

#define Bc   8
#define Sc   8192
#define Vc   64
#define Dc   256
#define DVc  32
#define DAGG 224     // D - DV
#define NTOK (Bc*Sc) // 65536
#define NBV  (Bc*Vc) // 512
#define CAP  Sc      // worst-case tokens per (b,v) segment
#define ABC_BLKS 32

// ---------------- scratch (device globals; no allocation) ----------------
__device__ float  g_A[DAGG], g_Bv[DAGG], g_C[DAGG];
__device__ float  g_part[ABC_BLKS][3][DAGG];
__device__ int    g_abc_ctr = 0;                           // self-resetting
__device__ float  g_pa[3][Dc], g_pb[3][Dc], g_pc[3][Dc];   // 0=q,1=k,2=v
__device__ float  g_Pvar[3][Vc][Dc];                       // var_emb @ W[0:32,:]
__device__ int    g_cnt[NBV];
__device__ float2 g_tok[NBV * CAP];                        // (val,tt) per segment
__device__ float  g_Ua[8][Dc], g_Ub[8][Dc], g_U0p[8][Dc];  // wo^T per-head projections
__device__ float  g_corr[Bc][Dc];
__device__ int    g_corrflag;
__device__ float  g_sumwv[Bc][8], g_sumwt[Bc][8];          // per (b,head) softmax scalars
__device__ float  g_p2[Bc][8];
__device__ int    g_ctr2[Bc];                              // zero-init, self-resetting
__device__ int    g_maskflags = 0;   // bit0: byte layout, bit1: float layout (OR idempotent)
__device__ float  g_sink;            // prefetch DCE guard

// ---------------- K1: parallel ABC collapse + mask detect + zero ----------------
__global__ void k_init(const float* __restrict__ me_w, const float* __restrict__ me_b,
                       const float* __restrict__ time_w, const float* __restrict__ time_b,
                       const float* __restrict__ agg_w, const float* __restrict__ agg_b,
                       const void* __restrict__ mask) {
    int blk = blockIdx.x;
    if (blk < ABC_BLKS) {
        int j = threadIdx.x;
        __shared__ bool isLast;
        if (j < DAGG) {
            float a = 0.f, b = 0.f, c = 0.f;
            int i0 = blk * 16;
            #pragma unroll
            for (int ii = 0; ii < 16; ii++) {
                int i = i0 + ii;
                if (i < 256) {
                    float w = agg_w[i * DAGG + j];
                    a += me_w[i] * w;  c += me_b[i] * w;
                } else {
                    int k = i - 256;
                    float w = agg_w[(256 + k) * DAGG + j];
                    b += time_w[k] * w;  c += time_b[k] * w;
                }
            }
            g_part[blk][0][j] = a;
            g_part[blk][1][j] = b;
            g_part[blk][2][j] = c;
        }
        __threadfence();
        __syncthreads();
        if (threadIdx.x == 0)
            isLast = (atomicAdd(&g_abc_ctr, 1) == ABC_BLKS - 1);
        __syncthreads();
        if (isLast) {
            if (j < DAGG) {
                float a = 0.f, b = 0.f, c = 0.f;
                #pragma unroll
                for (int r = 0; r < ABC_BLKS; r++) {
                    a += g_part[r][0][j];
                    b += g_part[r][1][j];
                    c += g_part[r][2][j];
                }
                g_A[j] = a; g_Bv[j] = b; g_C[j] = c + agg_b[j];
            }
            if (threadIdx.x == 0) g_abc_ctr = 0;
        }
    } else if (blk < ABC_BLKS + 8) {
        const unsigned int* w32 = (const unsigned int*)mask;
        int flags = 0;
        int base = (blk - ABC_BLKS) * 2048 + threadIdx.x;
        #pragma unroll
        for (int t = 0; t < 8; t++) {
            unsigned int w = w32[base + t * 256];
            if (w == 0x3f800000u) flags |= 2;
            else if (w > 1u)      flags |= 1;
        }
        __shared__ int sfl;
        if (threadIdx.x == 0) sfl = 0;
        __syncthreads();
        if (flags) atomicOr(&sfl, flags);
        __syncthreads();
        if (threadIdx.x == 0 && sfl) atomicOr(&g_maskflags, sfl);
    } else {
        int i = (blk - ABC_BLKS - 8) * 256 + threadIdx.x;   // 0..2815
        if (i < NBV) g_cnt[i] = 0;
        else if (i < NBV + Bc * Dc)        ((float*)g_corr)[i - NBV] = 0.f;
        else if (i < NBV + Bc * Dc + 64)   ((float*)g_sumwv)[i - NBV - Bc * Dc] = 0.f;
        else if (i < NBV + Bc * Dc + 128)  ((float*)g_sumwt)[i - NBV - Bc * Dc - 64] = 0.f;
        else if (i == NBV + Bc * Dc + 128) g_corrflag = 0;
    }
}

// ---------------- K2: Pvar/vec constants || token scan || U-vectors || prefetch ----------------
__global__ void k_mid(const float* __restrict__ var_emb,
                      const float* __restrict__ wq, const float* __restrict__ bq,
                      const float* __restrict__ wk, const float* __restrict__ bk,
                      const float* __restrict__ wv, const float* __restrict__ bv,
                      const int* __restrict__ fid, const void* __restrict__ mask,
                      const float* __restrict__ values, const float* __restrict__ times,
                      const float* __restrict__ wo, const float* __restrict__ bo,
                      const float* __restrict__ cw1) {
    int blk = blockIdx.x;
    int tid = threadIdx.x;
    if (blk < 201) {
        int p = blk / 67, row = blk % 67;
        const float* W  = (p == 0) ? wq : (p == 1 ? wk : wv);
        const float* bb = (p == 0) ? bq : (p == 1 ? bk : bv);
        int j = tid;
        if (row < Vc) {
            const float* ve = &var_emb[row * DVc];
            float s = 0.f;
            #pragma unroll
            for (int i = 0; i < DVc; i++) s += ve[i] * W[i * Dc + j];
            g_Pvar[p][row][j] = s;
        } else {
            const float* src = (row == Vc) ? g_A : (row == Vc + 1 ? g_Bv : g_C);
            float s = 0.f;
            #pragma unroll 8
            for (int i = 0; i < DAGG; i++) s += src[i] * W[(DVc + i) * Dc + j];
            if      (row == Vc)     g_pa[p][j] = s;
            else if (row == Vc + 1) g_pb[p][j] = s;
            else                    g_pc[p][j] = s + bb[j];
        }
    } else if (blk < 265) {
        // ---- token scan: 4 tokens per thread, vectorized loads ----
        int t4 = (blk - 201) * 256 + tid;   // token quad index
        int fl = g_maskflags;
        bool ok[4];
        if (fl & 2) {
            float4 m4 = ((const float4*)mask)[t4];
            ok[0] = m4.x != 0.f; ok[1] = m4.y != 0.f; ok[2] = m4.z != 0.f; ok[3] = m4.w != 0.f;
        } else if (fl & 1) {
            unsigned int u = ((const unsigned int*)mask)[t4];
            ok[0] = (u & 0xffu) != 0; ok[1] = (u & 0xff00u) != 0;
            ok[2] = (u & 0xff0000u) != 0; ok[3] = (u & 0xff000000u) != 0;
        } else {
            int4 m4 = ((const int4*)mask)[t4];
            ok[0] = m4.x != 0; ok[1] = m4.y != 0; ok[2] = m4.z != 0; ok[3] = m4.w != 0;
        }
        if (!(ok[0] | ok[1] | ok[2] | ok[3])) return;
        float4 vv = ((const float4*)values)[t4];
        float4 tt = ((const float4*)times)[t4];
        int4   ff = ((const int4*)fid)[t4];
        int b = (t4 * 4) >> 13;
        float va[4] = {vv.x, vv.y, vv.z, vv.w};
        float ta[4] = {tt.x, tt.y, tt.z, tt.w};
        int   fa[4] = {ff.x, ff.y, ff.z, ff.w};
        #pragma unroll
        for (int u = 0; u < 4; u++) {
            if (!ok[u]) continue;
            int bvx = b * Vc + fa[u];
            int pos = atomicAdd(&g_cnt[bvx], 1);
            g_tok[bvx * CAP + pos] = make_float2(va[u], ta[u]);
        }
    } else if (blk < 273) {
        // ---- U block for head h: Ua/Ub/U0p slices from A/B/C directly ----
        int h = blk - 265;
        int lane = tid & 31, grp = tid >> 5;
        __shared__ float sve[DVc];
        __shared__ float sp[8][DVc];
        __shared__ float pa2s[32], pb2s[32], sv0s[32];

        // column-sum of var_emb
        float p = 0.f;
        #pragma unroll
        for (int r = 0; r < 8; r++) p += var_emb[(grp * 8 + r) * DVc + lane];
        sp[grp][lane] = p;
        __syncthreads();
        if (grp == 0) {
            float s = 0.f;
            #pragma unroll
            for (int r = 0; r < 8; r++) s += sp[r][lane];
            sve[lane] = s;
        }
        __syncthreads();
        // pa2/pb2/SV0 for this head's 32 dims (direct from A/B/C)
        if (tid < 32) {
            int d = h * 32 + tid;
            float a = 0.f, b = 0.f, c = 0.f;
            #pragma unroll 8
            for (int i = 0; i < DAGG; i++) {
                float w = wv[(DVc + i) * Dc + d];
                a += g_A[i] * w;  b += g_Bv[i] * w;  c += g_C[i] * w;
            }
            float s0 = 64.f * (c + bv[d]);
            #pragma unroll
            for (int i = 0; i < DVc; i++) s0 += sve[i] * wv[i * Dc + d];
            pa2s[tid] = a; pb2s[tid] = b; sv0s[tid] = s0;
        }
        __syncthreads();
        // project through wo rows of this head
        int col = tid;
        float ua = 0.f, ub = 0.f, u0 = 0.f;
        #pragma unroll
        for (int k = 0; k < 32; k++) {
            float w = wo[(h * 32 + k) * Dc + col];
            ua += pa2s[k] * w;  ub += pb2s[k] * w;  u0 += sv0s[k] * w;
        }
        g_Ua[h][col]  = ua * (1.f / 64.f);
        g_Ub[h][col]  = ub * (1.f / 64.f);
        g_U0p[h][col] = u0 * (1.f / 64.f) + (h == 0 ? bo[col] : 0.f);
    } else {
        // ---- PF: warm L2 with cw1 for k_fin ----
        int chunk = blk - 273;                  // 0..15
        const float4* s4 = (const float4*)cw1;
        int base = chunk * 1024 + tid;
        float acc = 0.f;
        #pragma unroll
        for (int i = 0; i < 4; i++) {
            float4 w = __ldcg(&s4[base + i * 256]);
            acc += w.x + w.y + w.z + w.w;
        }
        if (acc == 1.2345e-37f) g_sink = acc;   // DCE guard, never taken
    }
}

// ---------------- K3: segmented attention -> per-head softmax scalars ----------------
__global__ void __launch_bounds__(256) k_attn(const int* __restrict__ fid,
                                              const float* __restrict__ values,
                                              const float* __restrict__ times) {
    int bvx = blockIdx.x;
    int b = bvx >> 6, v = bvx & (Vc - 1);
    int tid = threadIdx.x;             // dim index d = h*32+lane
    int h = tid >> 5, lane = tid & 31;
    int n = g_cnt[bvx];

    if (n == 0) {
        // all-masked segment: reference unmasks s=0 -> ctx = v_proj[b,0,:]
        int t0 = b * Sc;
        int f0 = fid[t0];
        atomicAdd(&g_corr[b][tid], g_Pvar[2][f0][tid] - g_Pvar[2][v][tid]);
        if (tid == 0) g_corrflag = 1;
        if (tid < 8)       atomicAdd(&g_sumwv[b][tid], values[t0]);
        else if (tid < 16) atomicAdd(&g_sumwt[b][tid - 8], times[t0]);
        return;
    }

    const float2* tok = &g_tok[bvx * CAP];

    // segment means (all warps redundantly; lane-parallel)
    float s_v = 0.f, s_t = 0.f;
    for (int i = lane; i < n; i += 32) {
        float2 vt = tok[i];
        s_v += vt.x; s_t += vt.y;
    }
    #pragma unroll
    for (int o = 16; o > 0; o >>= 1) {
        s_v += __shfl_xor_sync(0xffffffffu, s_v, o);
        s_t += __shfl_xor_sync(0xffffffffu, s_t, o);
    }
    float inv_n = 1.0f / (float)n;
    float mv = s_v * inv_n, mt = s_t * inv_n;

    // per-head affine score coefficients (warp h reduces over its 32 dims)
    float q  = g_Pvar[0][v][tid] + mv * g_pa[0][tid] + mt * g_pb[0][tid] + g_pc[0][tid];
    float kk = g_Pvar[1][v][tid] + g_pc[1][tid];
    const float scale = 0.17677669529663687f;  // 1/sqrt(32)
    float al = q * kk, be = q * g_pa[1][tid], ga = q * g_pb[1][tid];
    #pragma unroll
    for (int o = 16; o > 0; o >>= 1) {
        al += __shfl_xor_sync(0xffffffffu, al, o);
        be += __shfl_xor_sync(0xffffffffu, be, o);
        ga += __shfl_xor_sync(0xffffffffu, ga, o);
    }
    al *= scale; be *= scale; ga *= scale;

    // lane-parallel online softmax over this segment's tokens (one head per warp)
    float m = -1e30f, l = 0.f, sv = 0.f, st = 0.f;
    for (int i = lane; i < n; i += 32) {
        float2 vt = tok[i];
        float s  = al + be * vt.x + ga * vt.y;
        float nm = fmaxf(m, s);
        float c  = __expf(m - nm);
        float e  = __expf(s - nm);
        l  = l * c + e;
        sv = sv * c + e * vt.x;
        st = st * c + e * vt.y;
        m = nm;
    }
    #pragma unroll
    for (int o = 16; o > 0; o >>= 1) {
        float m2  = __shfl_xor_sync(0xffffffffu, m, o);
        float l2  = __shfl_xor_sync(0xffffffffu, l, o);
        float sv2 = __shfl_xor_sync(0xffffffffu, sv, o);
        float st2 = __shfl_xor_sync(0xffffffffu, st, o);
        float nm = fmaxf(m, m2);
        float c1 = __expf(m - nm), c2 = __expf(m2 - nm);
        l  = l * c1 + l2 * c2;
        sv = sv * c1 + sv2 * c2;
        st = st * c1 + st2 * c2;
        m = nm;
    }
    if (lane == 0) {
        atomicAdd(&g_sumwv[b][h], sv / l);
        atomicAdd(&g_sumwt[b][h], st / l);
    }
}

// ---------------- K4: FIN — rank-16 sf reconstruction + GEMV2 + out ----------------
__global__ void __launch_bounds__(256) k_fin(const float* __restrict__ wo,
                                             const float* __restrict__ cw1,
                                             const float* __restrict__ cb1,
                                             const float* __restrict__ cw2,
                                             const float* __restrict__ cb2,
                                             float* __restrict__ out) {
    int b = blockIdx.x >> 3, slice = blockIdx.x & 7;
    int tid = threadIdx.x;
    __shared__ float ssf[Dc];
    __shared__ float part[8][32];
    __shared__ float swv[8], swt[8];

    if (tid < 8)       swv[tid] = g_sumwv[b][tid];
    else if (tid < 16) swt[tid - 8] = g_sumwt[b][tid - 8];
    int cfl = g_corrflag;
    __syncthreads();

    // sf(b)[tid] = sum_h U0p + sum_h swv*Ua + swt*Ub (+ cold corr path)
    {
        float sf = 0.f;
        #pragma unroll
        for (int t = 0; t < 8; t++) sf += g_U0p[t][tid];
        #pragma unroll
        for (int t = 0; t < 8; t++)
            sf += swv[t] * g_Ua[t][tid] + swt[t] * g_Ub[t][tid];
        if (cfl) {
            float cd = 0.f;
            for (int d = 0; d < Dc; d++) cd += g_corr[b][d] * wo[d * Dc + tid];
            sf += cd * (1.f / 64.f);
        }
        ssf[tid] = sf;
    }
    __syncthreads();

    // GEMV2 slice + relu + dot (R6 f2 structure)
    int col = tid & 31, r = tid >> 5;
    int jg = slice * 32 + col;
    float acc = 0.f;
    #pragma unroll
    for (int ii = 0; ii < 32; ii++) {
        int i = r * 32 + ii;
        acc += ssf[i] * cw1[i * Dc + jg];
    }
    part[r][col] = acc;
    __syncthreads();
    if (r < 4) part[r][col] += part[r + 4][col];
    __syncthreads();
    if (r == 0) {
        float hh = part[0][col] + part[1][col] + part[2][col] + part[3][col] + cb1[jg];
        hh = fmaxf(hh, 0.f);
        float s = hh * cw2[jg];
        #pragma unroll
        for (int o = 16; o > 0; o >>= 1) s += __shfl_xor_sync(0xffffffffu, s, o);
        if (col == 0) {
            g_p2[b][slice] = s;
            __threadfence();
            int done = atomicAdd(&g_ctr2[b], 1);
            if (done == 7) {
                float tot = 0.f;
                #pragma unroll
                for (int k = 0; k < 8; k++) tot += g_p2[b][k];
                out[b] = tot + cb2[0];
                g_ctr2[b] = 0;   // reset for next replay
            }
        }
    }
}

// ---------------- launch ----------------
extern "C" void kernel_launch(void* const* d_in, const int* in_sizes, int n_in,
                              void* d_out, int out_size) {
    const float* times   = (const float*)d_in[0];
    const int*   fid     = (const int*)  d_in[1];
    const float* values  = (const float*)d_in[2];
    const void*  mask    = (const void*) d_in[3];
    const float* me_w    = (const float*)d_in[4];
    const float* me_b    = (const float*)d_in[5];
    const float* var_emb = (const float*)d_in[6];
    const float* time_w  = (const float*)d_in[7];
    const float* time_b  = (const float*)d_in[8];
    const float* agg_w   = (const float*)d_in[9];
    const float* agg_b   = (const float*)d_in[10];
    const float* wq = (const float*)d_in[11]; const float* bq  = (const float*)d_in[12];
    const float* wk = (const float*)d_in[13]; const float* bk  = (const float*)d_in[14];
    const float* wv = (const float*)d_in[15]; const float* bvv = (const float*)d_in[16];
    const float* wo = (const float*)d_in[17]; const float* bo  = (const float*)d_in[18];
    const float* cw1 = (const float*)d_in[19]; const float* cb1 = (const float*)d_in[20];
    const float* cw2 = (const float*)d_in[21]; const float* cb2 = (const float*)d_in[22];
    float* out = (float*)d_out;

    k_init <<<ABC_BLKS + 8 + 11, 256>>>(me_w, me_b, time_w, time_b, agg_w, agg_b, mask);
    k_mid  <<<201 + 64 + 8 + 16, 256>>>(var_emb, wq, bq, wk, bk, wv, bvv,
                                        fid, mask, values, times, wo, bo, cw1);
    k_attn <<<NBV, 256>>>(fid, values, times);
    k_fin  <<<64, 256>>>(wo, cw1, cb1, cw2, cb2, out);
}